// round 4
// baseline (speedup 1.0000x reference)
#include <cuda_runtime.h>
#include <stdint.h>

// Problem constants (fixed for GCN_69097433858735)
#define NN 100000
#define EE 3200000
#define FIN 128
#define HH 16
#define CC 2
#define SCAN_T 1024

// Static scratch (no runtime allocation allowed)
__device__ int   g_cnt [NN];        // in-degree (edges only, no self-loop)
__device__ float g_dinv[NN];        // rsqrt(deg+1)
__device__ int   g_off [NN + 1];    // CSR offsets by dst
__device__ int   g_cur [NN];        // fill cursors
__device__ int   g_csr [EE];        // CSR: src ids grouped by dst
__device__ __align__(16) float g_hs[NN * HH];  // (x@W1) * dinv[n]
__device__ __align__(8)  float g_gs[NN * CC];  // (relu_out @ W2) * dinv[n]

// ---------------------------------------------------------------------------
// 1) zero counts
__global__ void k_init(int n) {
    int i = blockIdx.x * blockDim.x + threadIdx.x;
    if (i < n) g_cnt[i] = 0;
}

// 2) count in-degrees from dst half of edge_index (int32!)
//    NOTE: reference uses jnp.int64 but JAX x64 is disabled by default,
//    so the actual buffer is int32: src = ei[0..E), dst = ei[E..2E).
__global__ void k_count(const int* __restrict__ ei, int e) {
    int i = blockIdx.x * blockDim.x + threadIdx.x;
    if (i >= e) return;
    int d = ei[e + i];
    if ((unsigned)d >= NN) d = 0;   // never crash; dtype surprise -> rel_err signal
    atomicAdd(&g_cnt[d], 1);
}

// 3) single-block exclusive scan of counts -> offsets, cursors, dinv
__global__ __launch_bounds__(SCAN_T) void k_scan(int n) {
    __shared__ int part[SCAN_T];
    int t = threadIdx.x;
    int chunk = (n + SCAN_T - 1) / SCAN_T;
    int lo = t * chunk;
    int hi = min(lo + chunk, n);

    int s = 0;
    for (int i = lo; i < hi; i++) s += g_cnt[i];
    part[t] = s;
    __syncthreads();
    // Hillis-Steele inclusive scan over partials
    for (int off = 1; off < SCAN_T; off <<= 1) {
        int v = (t >= off) ? part[t - off] : 0;
        __syncthreads();
        part[t] += v;
        __syncthreads();
    }
    int run = (t == 0) ? 0 : part[t - 1];
    for (int i = lo; i < hi; i++) {
        int c = g_cnt[i];
        g_off[i] = run;
        g_cur[i] = run;
        g_dinv[i] = rsqrtf((float)(c + 1));  // +1 = self-loop
        run += c;
    }
    if (t == SCAN_T - 1) g_off[n] = part[SCAN_T - 1];
}

// 4) fill CSR: slot = cursor[dst]++; csr[slot] = src   (int atomics only)
__global__ void k_fill(const int* __restrict__ ei, int e) {
    int i = blockIdx.x * blockDim.x + threadIdx.x;
    if (i >= e) return;
    int s = ei[i];
    int d = ei[e + i];
    if ((unsigned)s >= NN) s = 0;
    if ((unsigned)d >= NN) d = 0;
    int pos = atomicAdd(&g_cur[d], 1);
    g_csr[pos] = s;
}

// 5) hs[n] = (x[n] @ W1) * dinv[n]
__global__ __launch_bounds__(256) void k_gemm1(const float* __restrict__ x,
                                               const float* __restrict__ W1,
                                               int n) {
    __shared__ float sW1[FIN * HH];  // 8 KB
    for (int i = threadIdx.x; i < FIN * HH; i += blockDim.x)
        sW1[i] = W1[i];
    __syncthreads();

    int row = blockIdx.x * blockDim.x + threadIdx.x;
    if (row >= n) return;

    float acc[HH];
#pragma unroll
    for (int j = 0; j < HH; j++) acc[j] = 0.0f;

    const float4* xr = (const float4*)(x + (long long)row * FIN);
#pragma unroll 4
    for (int k4 = 0; k4 < FIN / 4; k4++) {
        float4 xv = __ldg(&xr[k4]);
        int k = k4 * 4;
#pragma unroll
        for (int j = 0; j < HH; j++) {
            acc[j] += xv.x * sW1[(k + 0) * HH + j];
            acc[j] += xv.y * sW1[(k + 1) * HH + j];
            acc[j] += xv.z * sW1[(k + 2) * HH + j];
            acc[j] += xv.w * sW1[(k + 3) * HH + j];
        }
    }
    float di = g_dinv[row];
    float4* hs4 = (float4*)(g_hs + (long long)row * HH);
#pragma unroll
    for (int q = 0; q < HH / 4; q++) {
        float4 v;
        v.x = acc[q * 4 + 0] * di;
        v.y = acc[q * 4 + 1] * di;
        v.z = acc[q * 4 + 2] * di;
        v.w = acc[q * 4 + 3] * di;
        hs4[q] = v;
    }
}

// 6) layer-1 aggregation (warp per node) + ReLU + GEMM2 fused.
//    Half-warp handles one edge (16 features); 2 edges per iteration.
__global__ __launch_bounds__(256) void k_agg1(const float* __restrict__ b1,
                                              const float* __restrict__ W2,
                                              int n) {
    int warp = (blockIdx.x * blockDim.x + threadIdx.x) >> 5;
    if (warp >= n) return;
    int lane = threadIdx.x & 31;
    int half = lane >> 4;     // 0 or 1
    int f    = lane & 15;     // feature index

    int beg = g_off[warp];
    int end = g_off[warp + 1];

    float acc = 0.0f;
    for (int e2 = beg + half; e2 < end; e2 += 2) {
        int s = g_csr[e2];                 // broadcast within half-warp
        acc += g_hs[s * HH + f];           // 64B coalesced per half
    }
    acc += __shfl_xor_sync(0xffffffffu, acc, 16);   // merge halves
    acc += g_hs[warp * HH + f];                     // self-loop term

    float di = g_dinv[warp];
    float o = fmaxf(di * acc + __ldg(&b1[f]), 0.0f);

    // gemm2 contribution: zero the duplicate upper half before reducing
    float c0 = o * __ldg(&W2[f * CC + 0]);
    float c1 = o * __ldg(&W2[f * CC + 1]);
    if (half) { c0 = 0.0f; c1 = 0.0f; }
#pragma unroll
    for (int off = 16; off >= 1; off >>= 1) {
        c0 += __shfl_xor_sync(0xffffffffu, c0, off);
        c1 += __shfl_xor_sync(0xffffffffu, c1, off);
    }
    if (lane == 0) {
        float2 v = make_float2(c0 * di, c1 * di);
        *(float2*)(g_gs + (long long)warp * CC) = v;
    }
}

// 7) layer-2 aggregation (warp per node) + final epilogue.
//    Lane pair handles one edge (2 channels); 16 edges per iteration.
__global__ __launch_bounds__(256) void k_agg2(const float* __restrict__ b2,
                                              float* __restrict__ out,
                                              int n) {
    int warp = (blockIdx.x * blockDim.x + threadIdx.x) >> 5;
    if (warp >= n) return;
    int lane = threadIdx.x & 31;
    int c = lane & 1;

    int beg = g_off[warp];
    int end = g_off[warp + 1];

    float acc = 0.0f;
    for (int e2 = beg + (lane >> 1); e2 < end; e2 += 16) {
        int s = g_csr[e2];
        acc += g_gs[s * CC + c];
    }
#pragma unroll
    for (int off = 16; off >= 2; off >>= 1)
        acc += __shfl_xor_sync(0xffffffffu, acc, off);
    // every same-parity lane now holds the channel-c total
    acc += g_gs[warp * CC + c];   // self-loop
    float r = g_dinv[warp] * acc + __ldg(&b2[c]);
    if (lane < 2) out[(long long)warp * CC + c] = r;
}

extern "C" void kernel_launch(void* const* d_in, const int* in_sizes, int n_in,
                              void* d_out, int out_size) {
    const float* x  = (const float*)d_in[0];
    const int*   ei = (const int*)d_in[1];    // int32! (JAX x64 disabled)
    const float* W1 = (const float*)d_in[2];
    const float* b1 = (const float*)d_in[3];
    const float* W2 = (const float*)d_in[4];
    const float* b2 = (const float*)d_in[5];
    float* out = (float*)d_out;

    int n = in_sizes[0] / FIN;     // 100000
    int e = in_sizes[1] / 2;       // 3200000

    const int T = 256;
    int gb_n  = (n + T - 1) / T;
    int gb_e  = (e + T - 1) / T;
    int gb_w  = (n * 32 + T - 1) / T;   // warp-per-node grids

    k_init <<<gb_n, T>>>(n);
    k_count<<<gb_e, T>>>(ei, e);
    k_scan <<<1, SCAN_T>>>(n);
    k_fill <<<gb_e, T>>>(ei, e);
    k_gemm1<<<gb_n, T>>>(x, W1, n);
    k_agg1 <<<gb_w, T>>>(b1, W2, n);
    k_agg2 <<<gb_w, T>>>(b2, out, n);
}

// round 5
// speedup vs baseline: 3.2307x; 3.2307x over previous
#include <cuda_runtime.h>
#include <stdint.h>

// Problem constants (fixed for GCN_69097433858735)
#define NN 100000
#define EE 3200000
#define FIN 128
#define HH 16
#define CC 2

// Static scratch (no runtime allocation allowed)
__device__ int   g_cnt [NN];                     // in-degree (edges only)
__device__ float g_dinv[NN];                     // rsqrt(deg+1)
__device__ __align__(16) float g_hs  [NN * HH];  // (x@W1) * dinv[n]
__device__ __align__(16) float g_acc1[NN * HH];
__device__ __align__(16) float g_gs  [NN * CC];  // (relu_out @ W2) * dinv[n]
__device__ __align__(16) float g_acc2[NN * CC];

// 1) zero degree counts
__global__ void k_init(int n) {
    int i = blockIdx.x * blockDim.x + threadIdx.x;
    if (i < n) g_cnt[i] = 0;
}

// 2) count in-degrees from dst half (edge_index is int32: JAX x64 disabled)
__global__ void k_count(const int* __restrict__ ei, int e) {
    int i = blockIdx.x * blockDim.x + threadIdx.x;
    if (i >= e) return;
    int d = ei[e + i];
    if ((unsigned)d >= NN) d = 0;
    atomicAdd(&g_cnt[d], 1);
}

// 3) dinv = rsqrt(deg+1)  (self-loop)
__global__ void k_dinv(int n) {
    int i = blockIdx.x * blockDim.x + threadIdx.x;
    if (i < n) g_dinv[i] = rsqrtf((float)(g_cnt[i] + 1));
}

// 4) hs[n] = (x[n] @ W1) * dinv[n]; zero acc1[n]
__global__ __launch_bounds__(256) void k_gemm1(const float* __restrict__ x,
                                               const float* __restrict__ W1,
                                               int n) {
    __shared__ float sW1[FIN * HH];  // 8 KB
    for (int i = threadIdx.x; i < FIN * HH; i += blockDim.x)
        sW1[i] = W1[i];
    __syncthreads();

    int row = blockIdx.x * blockDim.x + threadIdx.x;
    if (row >= n) return;

    float acc[HH];
#pragma unroll
    for (int j = 0; j < HH; j++) acc[j] = 0.0f;

    const float4* xr = (const float4*)(x + (long long)row * FIN);
#pragma unroll 4
    for (int k4 = 0; k4 < FIN / 4; k4++) {
        float4 xv = __ldg(&xr[k4]);
        int k = k4 * 4;
#pragma unroll
        for (int j = 0; j < HH; j++) {
            acc[j] += xv.x * sW1[(k + 0) * HH + j];
            acc[j] += xv.y * sW1[(k + 1) * HH + j];
            acc[j] += xv.z * sW1[(k + 2) * HH + j];
            acc[j] += xv.w * sW1[(k + 3) * HH + j];
        }
    }
    float di = g_dinv[row];
    float4* hs4 = (float4*)(g_hs   + (long long)row * HH);
    float4* ac4 = (float4*)(g_acc1 + (long long)row * HH);
    float4 z = make_float4(0.f, 0.f, 0.f, 0.f);
#pragma unroll
    for (int q = 0; q < HH / 4; q++) {
        float4 v;
        v.x = acc[q * 4 + 0] * di;
        v.y = acc[q * 4 + 1] * di;
        v.z = acc[q * 4 + 2] * di;
        v.w = acc[q * 4 + 3] * di;
        hs4[q] = v;
        ac4[q] = z;
    }
}

// 5) scatter layer 1: acc1[dst] += hs[src]  (4x float4 atomicAdd, sm_90+ RED)
__global__ __launch_bounds__(256) void k_scatter1(const int* __restrict__ ei, int e) {
    int i = blockIdx.x * blockDim.x + threadIdx.x;
    if (i >= e) return;
    int s = ei[i];
    int d = ei[e + i];
    if ((unsigned)s >= NN) s = 0;
    if ((unsigned)d >= NN) d = 0;
    const float4* hs4 = (const float4*)(g_hs + (long long)s * HH);
    float4* ap = (float4*)(g_acc1 + (long long)d * HH);
    float4 v0 = __ldg(&hs4[0]);
    float4 v1 = __ldg(&hs4[1]);
    float4 v2 = __ldg(&hs4[2]);
    float4 v3 = __ldg(&hs4[3]);
    atomicAdd(ap + 0, v0);
    atomicAdd(ap + 1, v1);
    atomicAdd(ap + 2, v2);
    atomicAdd(ap + 3, v3);
}

// 6) layer-1 epilogue + GEMM2: out1 = relu(dinv*(acc1+hs) + b1);
//    gs = (out1 @ W2) * dinv; zero acc2
__global__ __launch_bounds__(256) void k_fin1_gemm2(const float* __restrict__ b1,
                                                    const float* __restrict__ W2,
                                                    int n) {
    __shared__ float sW2[HH * CC];
    __shared__ float sb1[HH];
    for (int i = threadIdx.x; i < HH * CC; i += blockDim.x) sW2[i] = W2[i];
    for (int i = threadIdx.x; i < HH; i += blockDim.x) sb1[i] = b1[i];
    __syncthreads();

    int row = blockIdx.x * blockDim.x + threadIdx.x;
    if (row >= n) return;
    float di = g_dinv[row];

    const float4* ac4 = (const float4*)(g_acc1 + (long long)row * HH);
    const float4* hs4 = (const float4*)(g_hs + (long long)row * HH);
    float gc0 = 0.f, gc1 = 0.f;
#pragma unroll
    for (int q = 0; q < HH / 4; q++) {
        float4 a = ac4[q];
        float4 h = hs4[q];
        float o0 = fmaxf(di * (a.x + h.x) + sb1[q * 4 + 0], 0.f);
        float o1 = fmaxf(di * (a.y + h.y) + sb1[q * 4 + 1], 0.f);
        float o2 = fmaxf(di * (a.z + h.z) + sb1[q * 4 + 2], 0.f);
        float o3 = fmaxf(di * (a.w + h.w) + sb1[q * 4 + 3], 0.f);
        gc0 += o0 * sW2[(q * 4 + 0) * CC + 0] + o1 * sW2[(q * 4 + 1) * CC + 0]
             + o2 * sW2[(q * 4 + 2) * CC + 0] + o3 * sW2[(q * 4 + 3) * CC + 0];
        gc1 += o0 * sW2[(q * 4 + 0) * CC + 1] + o1 * sW2[(q * 4 + 1) * CC + 1]
             + o2 * sW2[(q * 4 + 2) * CC + 1] + o3 * sW2[(q * 4 + 3) * CC + 1];
    }
    *(float2*)(g_gs   + (long long)row * CC) = make_float2(gc0 * di, gc1 * di);
    *(float2*)(g_acc2 + (long long)row * CC) = make_float2(0.f, 0.f);
}

// 7) scatter layer 2: acc2[dst] += gs[src]  (float2 atomicAdd)
__global__ __launch_bounds__(256) void k_scatter2(const int* __restrict__ ei, int e) {
    int i = blockIdx.x * blockDim.x + threadIdx.x;
    if (i >= e) return;
    int s = ei[i];
    int d = ei[e + i];
    if ((unsigned)s >= NN) s = 0;
    if ((unsigned)d >= NN) d = 0;
    float2 v = __ldg((const float2*)(g_gs + (long long)s * CC));
    atomicAdd((float2*)(g_acc2 + (long long)d * CC), v);
}

// 8) final: out = dinv*(acc2+gs) + b2
__global__ void k_final(const float* __restrict__ b2, float* __restrict__ out, int n) {
    int row = blockIdx.x * blockDim.x + threadIdx.x;
    if (row >= n) return;
    float di = g_dinv[row];
    float2 a = *((const float2*)(g_acc2 + (long long)row * CC));
    float2 h = *((const float2*)(g_gs + (long long)row * CC));
    float2 o;
    o.x = di * (a.x + h.x) + b2[0];
    o.y = di * (a.y + h.y) + b2[1];
    *((float2*)(out + (long long)row * CC)) = o;
}

extern "C" void kernel_launch(void* const* d_in, const int* in_sizes, int n_in,
                              void* d_out, int out_size) {
    const float* x  = (const float*)d_in[0];
    const int*   ei = (const int*)d_in[1];    // int32 (JAX x64 disabled)
    const float* W1 = (const float*)d_in[2];
    const float* b1 = (const float*)d_in[3];
    const float* W2 = (const float*)d_in[4];
    const float* b2 = (const float*)d_in[5];
    float* out = (float*)d_out;

    int n = in_sizes[0] / FIN;     // 100000
    int e = in_sizes[1] / 2;       // 3200000

    const int T = 256;
    int gb_n = (n + T - 1) / T;
    int gb_e = (e + T - 1) / T;

    k_init      <<<gb_n, T>>>(n);
    k_count     <<<gb_e, T>>>(ei, e);
    k_dinv      <<<gb_n, T>>>(n);
    k_gemm1     <<<gb_n, T>>>(x, W1, n);
    k_scatter1  <<<gb_e, T>>>(ei, e);
    k_fin1_gemm2<<<gb_n, T>>>(b1, W2, n);
    k_scatter2  <<<gb_e, T>>>(ei, e);
    k_final     <<<gb_n, T>>>(b2, out, n);
}